// round 1
// baseline (speedup 1.0000x reference)
#include <cuda_runtime.h>
#include <cstdint>

// GraphConvNet: B=32, C=32, V=1024, L=13, support=3, order=2
// out[b,o,v,l] = bias[o] + sum_ct W[o,ct] * H[ct][b,v,l]
// H groups (ct = g*32 + c): g=0: x ; g=1..6: {A0,A0^2,A1,A1^2,A2,A2^2}^T applied to x.

#define V_N   1024
#define L_N   13
#define MCOLS 13312      // B*C*L = 32*32*13
#define MI    6144       // 6 * V_N  (rows of fused diffusion output)
#define CIN   224
#define COUT  64
#define NB    32         // batch

// ---------------- scratch (device globals: no runtime allocation) ----------------
__device__ float g_xt  [(size_t)V_N * MCOLS];      // [v][m]   54.5 MB
__device__ float g_Acat[(size_t)V_N * MI];         // [v][i]   25.2 MB, i = gA*1024 + w
__device__ float g_At  [3u * 1024u * 1024u];       // A^T per support (for A^2 GEMM)
__device__ float g_Acnt[3u * 1024u * 1024u];       // contiguous copy of A0,A1,A2
__device__ float g_yt  [(size_t)MI * MCOLS];       // [i][m]   327 MB

// ---------------- 1) x[bc][v][l] -> xt[v][bc*13+l] ----------------
__global__ void k_transpose_x(const float* __restrict__ x) {
    int idx = blockIdx.x * 256 + threadIdx.x;
    if (idx >= V_N * MCOLS) return;
    int v  = idx / MCOLS;
    int m  = idx - v * MCOLS;
    int bc = m / 13;
    int l  = m - bc * 13;
    g_xt[idx] = x[bc * MCOLS + v * 13 + l];
}

// ---------------- 2) copy A_s into Acat even blocks + contiguous staging ----------------
__global__ void k_copyA(const float* __restrict__ A0, const float* __restrict__ A1,
                        const float* __restrict__ A2) {
    int idx = blockIdx.x * 256 + threadIdx.x;
    if (idx >= 3 * 1024 * 1024) return;
    int s   = idx >> 20;
    int rem = idx & 0xFFFFF;
    int v   = rem >> 10;
    int w   = rem & 1023;
    const float* A = (s == 0) ? A0 : ((s == 1) ? A1 : A2);
    float val = A[rem];
    g_Acnt[idx] = val;
    g_Acat[(size_t)v * MI + s * 2048 + w] = val;   // column block (2s)*1024
}

// ---------------- 3) At[s][w][v] = A_s[v][w] (tiled transpose) ----------------
__global__ void k_transpose_A(const float* __restrict__ A0, const float* __restrict__ A1,
                              const float* __restrict__ A2) {
    __shared__ float tile[32][33];
    const float* A = (blockIdx.z == 0) ? A0 : ((blockIdx.z == 1) ? A1 : A2);
    float* At = g_At + ((size_t)blockIdx.z << 20);
    int wcol = blockIdx.x * 32 + threadIdx.x;
    int vrow = blockIdx.y * 32 + threadIdx.y;
#pragma unroll
    for (int j = 0; j < 32; j += 8)
        tile[threadIdx.y + j][threadIdx.x] = A[(size_t)(vrow + j) * 1024 + wcol];
    __syncthreads();
    int w2 = blockIdx.x * 32 + threadIdx.y;
    int v2 = blockIdx.y * 32 + threadIdx.x;
#pragma unroll
    for (int j = 0; j < 32; j += 8)
        At[(size_t)(w2 + j) * 1024 + v2] = tile[threadIdx.x][threadIdx.y + j];
}

// ---------------- 4) SGEMM (TN, both operands k-major): C[i][j] = sum_k A[k][i]*B[k][j]
// mode 0: A^2 batch  -> A=g_At+z<<20, B=g_Acnt+z<<20, C=g_Acat+1024+z*2048 (odd blocks)
// mode 1: fused diffusion -> A=g_Acat, B=g_xt, C=g_yt
// BM=BN=128, BK=8, 256 threads, 8x8 microtile. All dims are exact multiples.
__global__ __launch_bounds__(256) void k_sgemm(int mode, int K, int lda, int ldb, int ldc) {
    __shared__ float As[8][128];
    __shared__ float Bs[8][128];

    const float* A; const float* B; float* C;
    if (mode == 0) {
        size_t zoff = (size_t)blockIdx.z << 20;
        A = g_At + zoff;
        B = g_Acnt + zoff;
        C = g_Acat + 1024 + (size_t)blockIdx.z * 2048;
    } else {
        A = g_Acat; B = g_xt; C = g_yt;
    }

    int i0 = blockIdx.y * 128;
    int j0 = blockIdx.x * 128;
    int tid = threadIdx.x;
    int kk_l = tid >> 5;            // 0..7
    int col_l = (tid & 31) << 2;    // 0..124 step 4
    int tx = tid & 15;              // col group
    int ty = tid >> 4;              // row group

    float acc[8][8];
#pragma unroll
    for (int r = 0; r < 8; r++)
#pragma unroll
        for (int q = 0; q < 8; q++) acc[r][q] = 0.f;

    for (int k0 = 0; k0 < K; k0 += 8) {
        float4 av = *(const float4*)&A[(size_t)(k0 + kk_l) * lda + i0 + col_l];
        float4 bv = *(const float4*)&B[(size_t)(k0 + kk_l) * ldb + j0 + col_l];
        *(float4*)&As[kk_l][col_l] = av;
        *(float4*)&Bs[kk_l][col_l] = bv;
        __syncthreads();
#pragma unroll
        for (int kk = 0; kk < 8; kk++) {
            float4 a0 = *(const float4*)&As[kk][ty * 8];
            float4 a1 = *(const float4*)&As[kk][ty * 8 + 4];
            float4 b0 = *(const float4*)&Bs[kk][tx * 8];
            float4 b1 = *(const float4*)&Bs[kk][tx * 8 + 4];
            float ar[8] = {a0.x, a0.y, a0.z, a0.w, a1.x, a1.y, a1.z, a1.w};
            float br[8] = {b0.x, b0.y, b0.z, b0.w, b1.x, b1.y, b1.z, b1.w};
#pragma unroll
            for (int r = 0; r < 8; r++)
#pragma unroll
                for (int q = 0; q < 8; q++) acc[r][q] += ar[r] * br[q];
        }
        __syncthreads();
    }

#pragma unroll
    for (int r = 0; r < 8; r++) {
        size_t row = (size_t)(i0 + ty * 8 + r) * ldc + j0 + tx * 8;
        float4 v0 = make_float4(acc[r][0], acc[r][1], acc[r][2], acc[r][3]);
        float4 v1 = make_float4(acc[r][4], acc[r][5], acc[r][6], acc[r][7]);
        *(float4*)&C[row]     = v0;
        *(float4*)&C[row + 4] = v1;
    }
}

// ---------------- 5) final 1x1 conv: per-b GEMM M=64, K=224, N=13312 ----------------
__global__ __launch_bounds__(256) void k_final(const float* __restrict__ W,
                                               const float* __restrict__ bias,
                                               float* __restrict__ out) {
    __shared__ float Ws[16][64];
    __shared__ float Hs[16][128];

    int b  = blockIdx.y;
    int j0 = blockIdx.x * 128;
    int tid = threadIdx.x;
    int tx = tid & 15;   // cols: tx*8
    int ty = tid >> 4;   // rows: ty*4

    float acc[4][8];
#pragma unroll
    for (int r = 0; r < 4; r++)
#pragma unroll
        for (int q = 0; q < 8; q++) acc[r][q] = 0.f;

    for (int k0 = 0; k0 < CIN; k0 += 16) {
        // W tile, transposed into [kk][o]
#pragma unroll
        for (int q = 0; q < 4; q++) {
            int e = tid + 256 * q;       // 0..1023
            int o  = e >> 4;
            int kk = e & 15;
            Ws[kk][o] = W[o * CIN + k0 + kk];
        }
        // H tile (gather from xt / yt)
#pragma unroll
        for (int q = 0; q < 8; q++) {
            int e  = tid + 256 * q;      // 0..2047
            int kk = e >> 7;
            int jj = e & 127;
            int ct = k0 + kk;
            int g  = ct >> 5;
            int c  = ct & 31;
            int j  = j0 + jj;
            int v  = j / 13;
            int l  = j - v * 13;
            const float* src = (g == 0) ? g_xt
                                        : (g_yt + (size_t)(g - 1) * V_N * MCOLS);
            Hs[kk][jj] = src[(size_t)v * MCOLS + (b * 32 + c) * 13 + l];
        }
        __syncthreads();
#pragma unroll
        for (int kk = 0; kk < 16; kk++) {
            float rw[4];
#pragma unroll
            for (int r = 0; r < 4; r++) rw[r] = Ws[kk][ty * 4 + r];
            float4 h0 = *(const float4*)&Hs[kk][tx * 8];
            float4 h1 = *(const float4*)&Hs[kk][tx * 8 + 4];
            float rh[8] = {h0.x, h0.y, h0.z, h0.w, h1.x, h1.y, h1.z, h1.w};
#pragma unroll
            for (int r = 0; r < 4; r++)
#pragma unroll
                for (int q = 0; q < 8; q++) acc[r][q] += rw[r] * rh[q];
        }
        __syncthreads();
    }

#pragma unroll
    for (int r = 0; r < 4; r++) {
        int o = ty * 4 + r;
        float bo = bias[o];
        size_t row = (size_t)(b * 64 + o) * MCOLS + j0 + tx * 8;
        float4 v0 = make_float4(acc[r][0] + bo, acc[r][1] + bo, acc[r][2] + bo, acc[r][3] + bo);
        float4 v1 = make_float4(acc[r][4] + bo, acc[r][5] + bo, acc[r][6] + bo, acc[r][7] + bo);
        *(float4*)&out[row]     = v0;
        *(float4*)&out[row + 4] = v1;
    }
}

// ---------------- launcher ----------------
extern "C" void kernel_launch(void* const* d_in, const int* in_sizes, int n_in,
                              void* d_out, int out_size) {
    const float* x    = (const float*)d_in[0];
    const float* A0   = (const float*)d_in[1];
    const float* A1   = (const float*)d_in[2];
    const float* A2   = (const float*)d_in[3];
    const float* W    = (const float*)d_in[4];
    const float* bias = (const float*)d_in[5];
    float* out = (float*)d_out;

    // 1) transpose x -> xt[v][m]
    k_transpose_x<<<(V_N * MCOLS + 255) / 256, 256>>>(x);

    // 2) stage A's: contiguous copy + even Acat blocks
    k_copyA<<<(3 * 1024 * 1024 + 255) / 256, 256>>>(A0, A1, A2);

    // 3) A transposed (for A^2 GEMM in TN form)
    k_transpose_A<<<dim3(32, 32, 3), dim3(32, 8)>>>(A0, A1, A2);

    // 4) A^2 -> odd Acat blocks: C[v][w] = sum_u At[u][v] * A[u][w]
    k_sgemm<<<dim3(8, 8, 3), 256>>>(0, 1024, 1024, 1024, MI);

    // 5) fused diffusion GEMM: yt[i][m] = sum_v Acat[v][i] * xt[v][m]
    k_sgemm<<<dim3(MCOLS / 128, MI / 128, 1), 256>>>(1, 1024, MI, MCOLS, MCOLS);

    // 6) final 1x1 conv + bias
    k_final<<<dim3(MCOLS / 128, NB), 256>>>(W, bias, out);
}

// round 3
// speedup vs baseline: 2.5430x; 2.5430x over previous
#include <cuda_runtime.h>
#include <cuda_bf16.h>
#include <cstdint>

// GraphConvNet: B=32, C=32, V=1024, L=13, support=3, order=2
// yt[i][m] = sum_v T[i][v] * X[m][v], T = concat rows of {A_s^T, (A_s^T)^2}, X = x re-laid [m][v]
// out = W * [x ; yt] + b
// GEMMs on tensor cores via mma.sync bf16 with 3-term hi/lo split (fp32-accurate).

#define V_N   1024
#define MCOLS 13312      // B*C*L
#define MI    6144       // 6 * V_N
#define CIN   224
#define NB    32

// ---------------- scratch (device globals) ----------------
__device__ float g_Asq[3u * 1024u * 1024u];               // (A_s^T)^2 fp32
__device__ float g_yt [(size_t)MI * MCOLS];               // [i][m]
__device__ __nv_bfloat16 g_Abf_h[(size_t)MI * V_N];       // T split  [i][v]
__device__ __nv_bfloat16 g_Abf_l[(size_t)MI * V_N];
__device__ __nv_bfloat16 g_Bsq_h[3u * 1024u * 1024u];     // A_s split [v][u] (direct)
__device__ __nv_bfloat16 g_Bsq_l[3u * 1024u * 1024u];
__device__ __nv_bfloat16 g_Xbf_h[(size_t)MCOLS * V_N];    // X split  [m][v]
__device__ __nv_bfloat16 g_Xbf_l[(size_t)MCOLS * V_N];

// ================= helpers =================
__device__ __forceinline__ uint32_t smem_u32(const void* p) {
    uint32_t a;
    asm("{ .reg .u64 t; cvta.to.shared.u64 t, %1; cvt.u32.u64 %0, t; }" : "=r"(a) : "l"(p));
    return a;
}
#define CP16(s, g) asm volatile("cp.async.cg.shared.global [%0], [%1], 16;" :: "r"(s), "l"(g))
#define CP_COMMIT()  asm volatile("cp.async.commit_group;")
#define CP_WAIT1()   asm volatile("cp.async.wait_group 1;")

#define LDSM4(r, addr)                                                          \
    asm volatile("ldmatrix.sync.aligned.m8n8.x4.shared.b16 {%0,%1,%2,%3}, [%4];"\
        : "=r"((r)[0]), "=r"((r)[1]), "=r"((r)[2]), "=r"((r)[3]) : "r"(addr))

#define MMA16816(d, a, b0, b1)                                                  \
    asm volatile("mma.sync.aligned.m16n8k16.row.col.f32.bf16.bf16.f32 "         \
        "{%0,%1,%2,%3},{%4,%5,%6,%7},{%8,%9},{%0,%1,%2,%3};"                    \
        : "+f"((d)[0]), "+f"((d)[1]), "+f"((d)[2]), "+f"((d)[3])                \
        : "r"((a)[0]), "r"((a)[1]), "r"((a)[2]), "r"((a)[3]), "r"(b0), "r"(b1))

// ---------------- A_s -> split bf16 (direct, [v][u]) ----------------
__global__ void k_convA_direct(const float* __restrict__ A0, const float* __restrict__ A1,
                               const float* __restrict__ A2) {
    int idx = blockIdx.x * 256 + threadIdx.x;
    if (idx >= 3 * 1024 * 1024) return;
    int s = idx >> 20;
    int rem = idx & 0xFFFFF;
    const float* A = (s == 0) ? A0 : ((s == 1) ? A1 : A2);
    float f = A[rem];
    __nv_bfloat16 h = __float2bfloat16(f);
    g_Bsq_h[idx] = h;
    g_Bsq_l[idx] = __float2bfloat16(f - __bfloat162float(h));
}

// ---------------- A_s^T -> split bf16 into g_Abf rows s*2048 + w ----------------
__global__ void k_transposeA_conv(const float* __restrict__ A0, const float* __restrict__ A1,
                                  const float* __restrict__ A2) {
    __shared__ float t[32][33];
    int s = blockIdx.z;
    const float* A = (s == 0) ? A0 : ((s == 1) ? A1 : A2);
    int wb = blockIdx.x * 32, vb = blockIdx.y * 32;
#pragma unroll
    for (int j = 0; j < 32; j += 8)
        t[threadIdx.y + j][threadIdx.x] = A[(size_t)(vb + threadIdx.y + j) * 1024 + wb + threadIdx.x];
    __syncthreads();
#pragma unroll
    for (int j = 0; j < 32; j += 8) {
        float f = t[threadIdx.x][threadIdx.y + j];          // A[vb+tx][wb+ty+j]
        __nv_bfloat16 h = __float2bfloat16(f);
        size_t o = (size_t)(s * 2048 + wb + threadIdx.y + j) * 1024 + vb + threadIdx.x;
        g_Abf_h[o] = h;
        g_Abf_l[o] = __float2bfloat16(f - __bfloat162float(h));
    }
}

// ---------------- g_Asq -> split bf16 into g_Abf rows s*2048 + 1024 + w ----------------
__global__ void k_conv_sq() {
    int idx = blockIdx.x * 256 + threadIdx.x;
    if (idx >= 3 * 1024 * 1024) return;
    int s = idx >> 20;
    int rem = idx & 0xFFFFF;
    int w = rem >> 10, v = rem & 1023;
    float f = g_Asq[idx];
    __nv_bfloat16 h = __float2bfloat16(f);
    size_t o = (size_t)(s * 2048 + 1024 + w) * 1024 + v;
    g_Abf_h[o] = h;
    g_Abf_l[o] = __float2bfloat16(f - __bfloat162float(h));
}

// ---------------- x [bc][v][l] -> split bf16 [m=bc*13+l][v] ----------------
__global__ void k_convX(const float* __restrict__ x) {
    __shared__ float s[512 * 13];
    int bc = blockIdx.x >> 1;
    int vh = blockIdx.x & 1;
    const float* src = x + (size_t)bc * MCOLS + vh * 6656;
    for (int e = threadIdx.x; e < 6656; e += 256) s[e] = src[e];
    __syncthreads();
    for (int e = threadIdx.x; e < 6656; e += 256) {
        int l = e >> 9;
        int vloc = e & 511;
        float f = s[vloc * 13 + l];
        __nv_bfloat16 h = __float2bfloat16(f);
        size_t o = (size_t)(bc * 13 + l) * 1024 + vh * 512 + vloc;
        g_Xbf_h[o] = h;
        g_Xbf_l[o] = __float2bfloat16(f - __bfloat162float(h));
    }
}

// ---------------- tensor-core GEMM: C[i][j] = sum_v A[i][v]*B[j][v], 3-term split ----------------
// BM=128, BN=256, BK=64, 2-stage cp.async, 256 threads, warp tile 64x64.
// mode 0: per-support (A^T)^2 -> g_Asq ; mode 1: big diffusion -> g_yt
#define STAGE_BYTES 98304   // Ah 16K | Al 16K | Xh 32K | Xl 32K
#define GEMM_DYN    (2 * STAGE_BYTES)

__global__ __launch_bounds__(256, 1) void k_gemm(int mode) {
    extern __shared__ char sm[];
    const uint32_t sbase = smem_u32(sm);
    const int tid = threadIdx.x, lane = tid & 31, wid = tid >> 5;

    const __nv_bfloat16 *Ah, *Al, *Bh, *Bl;
    float* C;
    int ldc;
    if (mode == 0) {
        int s = blockIdx.z;
        Ah = g_Abf_h + (size_t)(s * 2048) * 1024;
        Al = g_Abf_l + (size_t)(s * 2048) * 1024;
        Bh = g_Bsq_h + ((size_t)s << 20);
        Bl = g_Bsq_l + ((size_t)s << 20);
        C  = g_Asq + ((size_t)s << 20);
        ldc = 1024;
    } else {
        Ah = g_Abf_h; Al = g_Abf_l;
        Bh = g_Xbf_h; Bl = g_Xbf_l;
        C  = g_yt;
        ldc = MCOLS;
    }
    const size_t i0 = (size_t)blockIdx.x * 128;
    const size_t j0 = (size_t)blockIdx.y * 256;

    // warp tile
    const int wm = (wid & 1) * 64;
    const int wn = (wid >> 1) * 64;
    // ldmatrix lane addressing (A: x4 over m16k16; B: x4 over two n8k16 tiles)
    const int arow = wm + (lane & 15);
    const int a_x7 = arow & 7;
    const int a_cs = lane >> 4;
    const int brow = wn + ((lane >> 4) << 3) + (lane & 7);
    const int b_x7 = brow & 7;
    const int b_cs = (lane >> 3) & 1;

    float acc[4][8][4];
#pragma unroll
    for (int mt = 0; mt < 4; mt++)
#pragma unroll
        for (int nt = 0; nt < 8; nt++)
#pragma unroll
            for (int q = 0; q < 4; q++) acc[mt][nt][q] = 0.f;

    // stage loader
    auto load_stage = [&](int st, int buf) {
        const int kv0 = st * 64;
        const uint32_t sb = sbase + buf * STAGE_BYTES;
#pragma unroll
        for (int q = 0; q < 4; q++) {
            int id = tid + 256 * q;
            int row = id >> 3, kc = id & 7;
            uint32_t sw = row * 128 + ((kc ^ (row & 7)) << 4);
            size_t go = (i0 + row) * 1024 + kv0 + kc * 8;
            CP16(sb + sw,         Ah + go);
            CP16(sb + 16384 + sw, Al + go);
        }
#pragma unroll
        for (int q = 0; q < 8; q++) {
            int id = tid + 256 * q;
            int row = id >> 3, kc = id & 7;
            uint32_t sw = row * 128 + ((kc ^ (row & 7)) << 4);
            size_t go = (j0 + row) * 1024 + kv0 + kc * 8;
            CP16(sb + 32768 + sw, Bh + go);
            CP16(sb + 65536 + sw, Bl + go);
        }
    };

    load_stage(0, 0);
    CP_COMMIT();

    for (int st = 0; st < 16; ++st) {
        if (st + 1 < 16) load_stage(st + 1, (st + 1) & 1);
        CP_COMMIT();
        CP_WAIT1();
        __syncthreads();

        const uint32_t sb = sbase + (st & 1) * STAGE_BYTES;
#pragma unroll
        for (int kk = 0; kk < 4; kk++) {
            uint32_t ah[4][4], al[4][4];
#pragma unroll
            for (int mt = 0; mt < 4; mt++) {
                uint32_t addr = sb + (arow + mt * 16) * 128 + (((kk * 2 + a_cs) ^ a_x7) << 4);
                LDSM4(ah[mt], addr);
                LDSM4(al[mt], addr + 16384);
            }
#pragma unroll
            for (int nt2 = 0; nt2 < 4; nt2++) {
                uint32_t bh[4], bl[4];
                uint32_t baddr = sb + 32768 + (brow + nt2 * 16) * 128 +
                                 (((kk * 2 + b_cs) ^ b_x7) << 4);
                LDSM4(bh, baddr);
                LDSM4(bl, baddr + 32768);
#pragma unroll
                for (int mt = 0; mt < 4; mt++) {
                    MMA16816(acc[mt][nt2 * 2],     ah[mt], bh[0], bh[1]);
                    MMA16816(acc[mt][nt2 * 2],     ah[mt], bl[0], bl[1]);
                    MMA16816(acc[mt][nt2 * 2],     al[mt], bh[0], bh[1]);
                    MMA16816(acc[mt][nt2 * 2 + 1], ah[mt], bh[2], bh[3]);
                    MMA16816(acc[mt][nt2 * 2 + 1], ah[mt], bl[2], bl[3]);
                    MMA16816(acc[mt][nt2 * 2 + 1], al[mt], bh[2], bh[3]);
                }
            }
        }
        __syncthreads();
    }

    // epilogue
    const int crow = lane >> 2;
    const int ccol = (lane & 3) * 2;
#pragma unroll
    for (int mt = 0; mt < 4; mt++) {
        size_t rbase = (i0 + wm + mt * 16 + crow) * (size_t)ldc + j0 + wn + ccol;
#pragma unroll
        for (int nt = 0; nt < 8; nt++) {
            float* p = C + rbase + nt * 8;
            *(float2*)p             = make_float2(acc[mt][nt][0], acc[mt][nt][1]);
            *(float2*)(p + 8 * ldc) = make_float2(acc[mt][nt][2], acc[mt][nt][3]);
        }
    }
}

// ---------------- final 1x1 conv: per-b GEMM M=64, K=224, N=13312 ----------------
__global__ __launch_bounds__(256) void k_final(const float* __restrict__ x,
                                               const float* __restrict__ W,
                                               const float* __restrict__ bias,
                                               float* __restrict__ out) {
    __shared__ float Ws[16][64];
    __shared__ float Hs[16][128];

    int b  = blockIdx.y;
    int j0 = blockIdx.x * 128;
    int tid = threadIdx.x;
    int tx = tid & 15, ty = tid >> 4;

    float acc[4][8];
#pragma unroll
    for (int r = 0; r < 4; r++)
#pragma unroll
        for (int q = 0; q < 8; q++) acc[r][q] = 0.f;

    for (int k0 = 0; k0 < CIN; k0 += 16) {
#pragma unroll
        for (int q = 0; q < 4; q++) {
            int e = tid + 256 * q;
            int o  = e >> 4;
            int kk = e & 15;
            Ws[kk][o] = W[o * CIN + k0 + kk];
        }
#pragma unroll
        for (int q = 0; q < 8; q++) {
            int e  = tid + 256 * q;
            int kk = e >> 7;
            int jj = e & 127;
            int ct = k0 + kk;
            int g  = ct >> 5;
            int c  = ct & 31;
            int j  = j0 + jj;
            int v  = j / 13;
            int l  = j - v * 13;
            float val;
            if (g == 0)
                val = x[(size_t)(b * 32 + c) * MCOLS + v * 13 + l];
            else
                val = g_yt[((size_t)(g - 1) * V_N + v) * MCOLS + (b * 32 + c) * 13 + l];
            Hs[kk][jj] = val;
        }
        __syncthreads();
#pragma unroll
        for (int kk = 0; kk < 16; kk++) {
            float rw[4];
#pragma unroll
            for (int r = 0; r < 4; r++) rw[r] = Ws[kk][ty * 4 + r];
            float4 h0 = *(const float4*)&Hs[kk][tx * 8];
            float4 h1 = *(const float4*)&Hs[kk][tx * 8 + 4];
            float rh[8] = {h0.x, h0.y, h0.z, h0.w, h1.x, h1.y, h1.z, h1.w};
#pragma unroll
            for (int r = 0; r < 4; r++)
#pragma unroll
                for (int q = 0; q < 8; q++) acc[r][q] += rw[r] * rh[q];
        }
        __syncthreads();
    }
#pragma unroll
    for (int r = 0; r < 4; r++) {
        int o = ty * 4 + r;
        float bo = bias[o];
        size_t row = (size_t)(b * 64 + o) * MCOLS + j0 + tx * 8;
        *(float4*)&out[row]     = make_float4(acc[r][0] + bo, acc[r][1] + bo, acc[r][2] + bo, acc[r][3] + bo);
        *(float4*)&out[row + 4] = make_float4(acc[r][4] + bo, acc[r][5] + bo, acc[r][6] + bo, acc[r][7] + bo);
    }
}

// ---------------- launcher ----------------
extern "C" void kernel_launch(void* const* d_in, const int* in_sizes, int n_in,
                              void* d_out, int out_size) {
    const float* x    = (const float*)d_in[0];
    const float* A0   = (const float*)d_in[1];
    const float* A1   = (const float*)d_in[2];
    const float* A2   = (const float*)d_in[3];
    const float* W    = (const float*)d_in[4];
    const float* bias = (const float*)d_in[5];
    float* out = (float*)d_out;

    cudaFuncSetAttribute(k_gemm, cudaFuncAttributeMaxDynamicSharedMemorySize, GEMM_DYN);

    // stage operands
    k_convA_direct<<<(3 * 1024 * 1024 + 255) / 256, 256>>>(A0, A1, A2);
    k_transposeA_conv<<<dim3(32, 32, 3), dim3(32, 8)>>>(A0, A1, A2);
    k_convX<<<2048, 256>>>(x);

    // (A^T)^2 via tensor cores, then split-convert into g_Abf odd blocks
    k_gemm<<<dim3(8, 4, 3), 256, GEMM_DYN>>>(0);
    k_conv_sq<<<(3 * 1024 * 1024 + 255) / 256, 256>>>();

    // fused diffusion GEMM (grid.x = i-tiles for A reuse per wave)
    k_gemm<<<dim3(48, 52, 1), 256, GEMM_DYN>>>(1);

    // final 1x1 conv + bias
    k_final<<<dim3(MCOLS / 128, NB), 256>>>(x, W, bias, out);
}

// round 5
// speedup vs baseline: 4.0388x; 1.5882x over previous
#include <cuda_runtime.h>
#include <cuda_fp16.h>
#include <cstdint>

// GraphConvNet: B=32, C=32, V=1024, L=13, support=3, order=2
// yt[i][m] = sum_v T[i][v] * X[m][v], T = concat{A_s^T, (A_s^T)^2}, X = x [m][v]
// out = W * [x ; yt] + b
// fp16 tensor cores: T exact via hi+lo split (2-term), X rounded once.

#define V_N   1024
#define MCOLS 13312      // B*C*L
#define MI    6144       // 6 * V_N
#define CIN   224
#define NB    32
#define PAD_E 232        // Hf/W smem pitch in fp16 elements (464B)

// ---------------- scratch (device globals) ----------------
__device__ float  g_Asq[3u * 1024u * 1024u];            // (A_s^T)^2 fp32
__device__ __half g_yt [(size_t)MI * MCOLS];            // [i][m] fp16
__device__ __half g_Abf_h[(size_t)MI * V_N];            // T split [i][v]
__device__ __half g_Abf_l[(size_t)MI * V_N];
__device__ __half g_Bh [3u * 1024u * 1024u];            // A_s direct [u][v] fp16
__device__ __half g_Xh [(size_t)MCOLS * V_N];           // X [m][v] fp16
__device__ __half g_Hf [(size_t)NB * MCOLS * CIN];      // [(b,v,l)][ct] fp16
__device__ __half g_Wh [64 * CIN];
__device__ __half g_Wl [64 * CIN];

// ================= helpers =================
__device__ __forceinline__ uint32_t smem_u32(const void* p) {
    uint32_t a;
    asm("{ .reg .u64 t; cvta.to.shared.u64 t, %1; cvt.u32.u64 %0, t; }" : "=r"(a) : "l"(p));
    return a;
}
#define CP16(s, g) asm volatile("cp.async.cg.shared.global [%0], [%1], 16;" :: "r"(s), "l"(g))
#define CP_COMMIT() asm volatile("cp.async.commit_group;")
#define CP_WAIT2()  asm volatile("cp.async.wait_group 2;")
#define CP_WAIT0()  asm volatile("cp.async.wait_group 0;")

#define LDSM4(r, addr)                                                          \
    asm volatile("ldmatrix.sync.aligned.m8n8.x4.shared.b16 {%0,%1,%2,%3}, [%4];"\
        : "=r"((r)[0]), "=r"((r)[1]), "=r"((r)[2]), "=r"((r)[3]) : "r"(addr))

#define MMAH(d, a, b0, b1)                                                      \
    asm volatile("mma.sync.aligned.m16n8k16.row.col.f32.f16.f16.f32 "           \
        "{%0,%1,%2,%3},{%4,%5,%6,%7},{%8,%9},{%0,%1,%2,%3};"                    \
        : "+f"((d)[0]), "+f"((d)[1]), "+f"((d)[2]), "+f"((d)[3])                \
        : "r"((a)[0]), "r"((a)[1]), "r"((a)[2]), "r"((a)[3]), "r"(b0), "r"(b1))

// ---------------- A_s -> fp16 direct [u][v] ----------------
__global__ void k_convA_direct(const float* __restrict__ A0, const float* __restrict__ A1,
                               const float* __restrict__ A2) {
    int idx = blockIdx.x * 256 + threadIdx.x;
    if (idx >= 3 * 1024 * 1024) return;
    int s = idx >> 20;
    int rem = idx & 0xFFFFF;
    const float* A = (s == 0) ? A0 : ((s == 1) ? A1 : A2);
    g_Bh[idx] = __float2half(A[rem]);
}

// ---------------- A_s^T -> split fp16 into g_Abf rows s*2048 + w ----------------
__global__ void k_transposeA_conv(const float* __restrict__ A0, const float* __restrict__ A1,
                                  const float* __restrict__ A2) {
    __shared__ float t[32][33];
    int s = blockIdx.z;
    const float* A = (s == 0) ? A0 : ((s == 1) ? A1 : A2);
    int wb = blockIdx.x * 32, vb = blockIdx.y * 32;
#pragma unroll
    for (int j = 0; j < 32; j += 8)
        t[threadIdx.y + j][threadIdx.x] = A[(size_t)(vb + threadIdx.y + j) * 1024 + wb + threadIdx.x];
    __syncthreads();
#pragma unroll
    for (int j = 0; j < 32; j += 8) {
        float f = t[threadIdx.x][threadIdx.y + j];
        __half h = __float2half(f);
        size_t o = (size_t)(s * 2048 + wb + threadIdx.y + j) * 1024 + vb + threadIdx.x;
        g_Abf_h[o] = h;
        g_Abf_l[o] = __float2half(f - __half2float(h));
    }
}

// ---------------- g_Asq -> split fp16 into g_Abf rows s*2048 + 1024 + w ----------------
__global__ void k_conv_sq() {
    int idx = blockIdx.x * 256 + threadIdx.x;
    if (idx >= 3 * 1024 * 1024) return;
    int s = idx >> 20;
    int rem = idx & 0xFFFFF;
    int w = rem >> 10, v = rem & 1023;
    float f = g_Asq[idx];
    __half h = __float2half(f);
    size_t o = (size_t)(s * 2048 + 1024 + w) * 1024 + v;
    g_Abf_h[o] = h;
    g_Abf_l[o] = __float2half(f - __half2float(h));
}

// ---------------- x [bc][v][l] -> fp16 [m][v] ----------------
__global__ void k_convX(const float* __restrict__ x) {
    __shared__ float s[512 * 13];
    int bc = blockIdx.x >> 1;
    int vh = blockIdx.x & 1;
    const float* src = x + (size_t)bc * MCOLS + vh * 6656;
    for (int e = threadIdx.x; e < 6656; e += 256) s[e] = src[e];
    __syncthreads();
    for (int e = threadIdx.x; e < 6656; e += 256) {
        int l = e >> 9;
        int vloc = e & 511;
        g_Xh[(size_t)(bc * 13 + l) * 1024 + vh * 512 + vloc] = __float2half(s[vloc * 13 + l]);
    }
}

// ---------------- W -> split fp16 ----------------
__global__ void k_convW(const float* __restrict__ W) {
    int idx = blockIdx.x * 256 + threadIdx.x;
    if (idx >= 64 * CIN) return;
    float f = W[idx];
    __half h = __float2half(f);
    g_Wh[idx] = h;
    g_Wl[idx] = __float2half(f - __half2float(h));
}

// ---------------- main GEMM: C[i][j] = sum_v (Ah+Al)[i][v] * Bh[j][v] ----------------
// BM=128, BN=256, BK=64, 3-stage cp.async, 256 thr, warp tile 64x64, 2-term fp16.
#define STAGE_B 65536          // Ah 16K | Al 16K | Xh 32K
#define GEMM_DYN (3 * STAGE_B)

__global__ __launch_bounds__(256, 1) void k_gemm(int mode) {
    extern __shared__ char sm[];
    const uint32_t sbase = smem_u32(sm);
    const int tid = threadIdx.x, lane = tid & 31, wid = tid >> 5;

    const __half *Ah, *Al, *Bh;
    if (mode == 0) {
        int s = blockIdx.z;
        Ah = g_Abf_h + (size_t)(s * 2048) * 1024;
        Al = g_Abf_l + (size_t)(s * 2048) * 1024;
        Bh = g_Bh + ((size_t)s << 20);
    } else {
        Ah = g_Abf_h; Al = g_Abf_l; Bh = g_Xh;
    }
    const size_t i0 = (size_t)blockIdx.x * 128;
    const size_t j0 = (size_t)blockIdx.y * 256;

    const int wm = (wid & 1) * 64;
    const int wn = (wid >> 1) * 64;
    const int arow = wm + (lane & 15);
    const int a_x7 = arow & 7;
    const int a_cs = lane >> 4;
    const int brow = wn + ((lane >> 4) << 3) + (lane & 7);
    const int b_x7 = brow & 7;
    const int b_cs = (lane >> 3) & 1;

    float acc[4][8][4];
#pragma unroll
    for (int mt = 0; mt < 4; mt++)
#pragma unroll
        for (int nt = 0; nt < 8; nt++)
#pragma unroll
            for (int q = 0; q < 4; q++) acc[mt][nt][q] = 0.f;

    auto load_stage = [&](int st, int buf) {
        const int kv0 = st * 64;
        const uint32_t sb = sbase + buf * STAGE_B;
#pragma unroll
        for (int q = 0; q < 4; q++) {
            int id = tid + 256 * q;
            int row = id >> 3, kc = id & 7;
            uint32_t sw = row * 128 + ((kc ^ (row & 7)) << 4);
            size_t go = (i0 + row) * 1024 + kv0 + kc * 8;
            CP16(sb + sw,         Ah + go);
            CP16(sb + 16384 + sw, Al + go);
        }
#pragma unroll
        for (int q = 0; q < 8; q++) {
            int id = tid + 256 * q;
            int row = id >> 3, kc = id & 7;
            uint32_t sw = row * 128 + ((kc ^ (row & 7)) << 4);
            CP16(sb + 32768 + sw, Bh + (j0 + row) * 1024 + kv0 + kc * 8);
        }
    };

    load_stage(0, 0); CP_COMMIT();
    load_stage(1, 1); CP_COMMIT();
    load_stage(2, 2); CP_COMMIT();

    int buf = 0;
    for (int st = 0; st < 16; ++st) {
        CP_WAIT2();
        __syncthreads();
        const uint32_t sb = sbase + buf * STAGE_B;
#pragma unroll
        for (int kk = 0; kk < 4; kk++) {
            uint32_t ah[4][4], al[4][4];
#pragma unroll
            for (int mt = 0; mt < 4; mt++) {
                uint32_t addr = sb + (arow + mt * 16) * 128 + (((kk * 2 + a_cs) ^ a_x7) << 4);
                LDSM4(ah[mt], addr);
                LDSM4(al[mt], addr + 16384);
            }
#pragma unroll
            for (int nt2 = 0; nt2 < 4; nt2++) {
                uint32_t bh[4];
                LDSM4(bh, sb + 32768 + (brow + nt2 * 16) * 128 +
                          (((kk * 2 + b_cs) ^ b_x7) << 4));
#pragma unroll
                for (int mt = 0; mt < 4; mt++) {
                    MMAH(acc[mt][nt2 * 2],     ah[mt], bh[0], bh[1]);
                    MMAH(acc[mt][nt2 * 2],     al[mt], bh[0], bh[1]);
                    MMAH(acc[mt][nt2 * 2 + 1], ah[mt], bh[2], bh[3]);
                    MMAH(acc[mt][nt2 * 2 + 1], al[mt], bh[2], bh[3]);
                }
            }
        }
        __syncthreads();
        if (st + 3 < 16) load_stage(st + 3, buf);
        CP_COMMIT();
        buf = (buf + 1 == 3) ? 0 : buf + 1;
    }

    const int crow = lane >> 2;
    const int ccol = (lane & 3) * 2;
    if (mode == 0) {
        float* C = g_Asq + ((size_t)blockIdx.z << 20);
#pragma unroll
        for (int mt = 0; mt < 4; mt++) {
            size_t rbase = (i0 + wm + mt * 16 + crow) * 1024 + j0 + wn + ccol;
#pragma unroll
            for (int nt = 0; nt < 8; nt++) {
                float* p = C + rbase + nt * 8;
                *(float2*)p              = make_float2(acc[mt][nt][0], acc[mt][nt][1]);
                *(float2*)(p + 8 * 1024) = make_float2(acc[mt][nt][2], acc[mt][nt][3]);
            }
        }
    } else {
#pragma unroll
        for (int mt = 0; mt < 4; mt++) {
            size_t rbase = (i0 + wm + mt * 16 + crow) * MCOLS + j0 + wn + ccol;
#pragma unroll
            for (int nt = 0; nt < 8; nt++) {
                __half* p = g_yt + rbase + nt * 8;
                *(__half2*)p               = __floats2half2_rn(acc[mt][nt][0], acc[mt][nt][1]);
                *(__half2*)(p + 8 * MCOLS) = __floats2half2_rn(acc[mt][nt][2], acc[mt][nt][3]);
            }
        }
    }
}

// ---------------- transpose/pack: Hf[(b,v,l)][ct] from x + g_yt ----------------
// grid (128 vblk, 32 b); CTA: 8 v-values (104 n-rows).
#define TRANS_DYN (48 * 416 * 2 + 32 * 104 * 4)   // yt halfs + x floats

__global__ __launch_bounds__(256) void k_trans(const float* __restrict__ x) {
    extern __shared__ char sm[];
    __half* syt = (__half*)sm;                 // [48][416]
    float*  sx  = (float*)(sm + 48 * 416 * 2); // [32][104]
    const int v0 = blockIdx.x * 8;
    const int b  = blockIdx.y;
    const int tid = threadIdx.x;

    // load yt rows (g,vi): 48 rows x 416 halfs, vectorized 16B
    for (int e = tid; e < 48 * 52; e += 256) {
        int r = e / 52, q = e - r * 52;
        int g = r >> 3, vi = r & 7;
        const __half* src = g_yt + ((size_t)(g * 1024 + v0 + vi)) * MCOLS + b * 416 + q * 8;
        *(uint4*)(syt + r * 416 + q * 8) = *(const uint4*)src;
    }
    // load x rows (c): 32 rows x 104 floats
    for (int e = tid; e < 32 * 26; e += 256) {
        int c = e / 26, q = e - c * 26;
        const float* src = x + (size_t)(b * 32 + c) * MCOLS + v0 * 13 + q * 4;
        *(float4*)(sx + c * 104 + q * 4) = *(const float4*)src;
    }
    __syncthreads();

    // write Hf: 104 rows x 28 chunks of 8 halfs
    for (int e = tid; e < 104 * 28; e += 256) {
        int n = e / 28, q = e - n * 28;
        int vi = n / 13, l = n - vi * 13;
        int ct0 = q * 8;
        union { uint4 u; __half2 h[4]; } pk;
        if (q < 4) {
            int c0 = ct0;
#pragma unroll
            for (int i = 0; i < 4; i++)
                pk.h[i] = __floats2half2_rn(sx[(c0 + 2 * i) * 104 + n],
                                            sx[(c0 + 2 * i + 1) * 104 + n]);
        } else {
            int g = ct0 >> 5, c0 = ct0 & 31;
            const __half* row = syt + ((g - 1) * 8 + vi) * 416 + l;
#pragma unroll
            for (int i = 0; i < 4; i++)
                pk.h[i] = __halves2half2(row[(c0 + 2 * i) * 13], row[(c0 + 2 * i + 1) * 13]);
        }
        *(uint4*)(g_Hf + ((size_t)(b * MCOLS + v0 * 13 + n)) * CIN + ct0) = pk.u;
    }
}

// ---------------- final MMA: out[(b,o)][n] = (Wh+Wl) * Hf + bias ----------------
// grid (104 n-tiles, 32 b); M=64, N=128, K=224 all staged.
#define FIN_WH   0
#define FIN_WL   (64 * PAD_E * 2)
#define FIN_HS   (128 * PAD_E * 2)
#define FIN_DYN  (FIN_WL + FIN_HS + 128 * PAD_E * 2)

__global__ __launch_bounds__(256, 1) void k_final(const float* __restrict__ bias,
                                                  float* __restrict__ out) {
    extern __shared__ char sm[];
    const uint32_t sbase = smem_u32(sm);
    const int tid = threadIdx.x, lane = tid & 31, wid = tid >> 5;
    const int b = blockIdx.y;
    const int j0 = blockIdx.x * 128;

    // stage W (split) and Hf panel, 16B chunks
    for (int e = tid; e < 64 * 28; e += 256) {
        int r = e / 28, q = e - r * 28;
        CP16(sbase + FIN_WH + r * 464 + q * 16, g_Wh + r * CIN + q * 8);
        CP16(sbase + FIN_WL + r * 464 + q * 16, g_Wl + r * CIN + q * 8);
    }
    for (int e = tid; e < 128 * 28; e += 256) {
        int r = e / 28, q = e - r * 28;
        CP16(sbase + FIN_HS + r * 464 + q * 16,
             g_Hf + ((size_t)(b * MCOLS + j0 + r)) * CIN + q * 8);
    }
    CP_COMMIT();
    CP_WAIT0();
    __syncthreads();

    const int wm = (wid & 1) * 32;
    const int wn = (wid >> 1) * 32;
    const int arow_l = lane & 15;
    const int a_cs = lane >> 4;
    const int brow_l = ((lane >> 4) << 3) + (lane & 7);
    const int b_cs = (lane >> 3) & 1;

    float acc[2][4][4];
#pragma unroll
    for (int mt = 0; mt < 2; mt++)
#pragma unroll
        for (int nt = 0; nt < 4; nt++)
#pragma unroll
            for (int q = 0; q < 4; q++) acc[mt][nt][q] = 0.f;

#pragma unroll
    for (int kc = 0; kc < 14; kc++) {
        uint32_t wh[2][4], wl[2][4];
#pragma unroll
        for (int mt = 0; mt < 2; mt++) {
            uint32_t ao = (wm + mt * 16 + arow_l) * 464 + (kc * 2 + a_cs) * 16;
            LDSM4(wh[mt], sbase + FIN_WH + ao);
            LDSM4(wl[mt], sbase + FIN_WL + ao);
        }
#pragma unroll
        for (int nt2 = 0; nt2 < 2; nt2++) {
            uint32_t bh[4];
            LDSM4(bh, sbase + FIN_HS + (wn + nt2 * 16 + brow_l) * 464 +
                      (kc * 2 + b_cs) * 16);
#pragma unroll
            for (int mt = 0; mt < 2; mt++) {
                MMAH(acc[mt][nt2 * 2],     wh[mt], bh[0], bh[1]);
                MMAH(acc[mt][nt2 * 2],     wl[mt], bh[0], bh[1]);
                MMAH(acc[mt][nt2 * 2 + 1], wh[mt], bh[2], bh[3]);
                MMAH(acc[mt][nt2 * 2 + 1], wl[mt], bh[2], bh[3]);
            }
        }
    }

    const int crow = lane >> 2;
    const int ccol = (lane & 3) * 2;
#pragma unroll
    for (int mt = 0; mt < 2; mt++) {
        int o = wm + mt * 16 + crow;
        float b0 = bias[o], b1 = bias[o + 8];
        size_t r0 = (size_t)(b * 64 + o) * MCOLS + j0 + wn + ccol;
#pragma unroll
        for (int nt = 0; nt < 4; nt++) {
            float* p = out + r0 + nt * 8;
            *(float2*)p               = make_float2(acc[mt][nt][0] + b0, acc[mt][nt][1] + b0);
            *(float2*)(p + 8 * MCOLS) = make_float2(acc[mt][nt][2] + b1, acc[mt][nt][3] + b1);
        }
    }
}

// ---------------- launcher ----------------
extern "C" void kernel_launch(void* const* d_in, const int* in_sizes, int n_in,
                              void* d_out, int out_size) {
    const float* x    = (const float*)d_in[0];
    const float* A0   = (const float*)d_in[1];
    const float* A1   = (const float*)d_in[2];
    const float* A2   = (const float*)d_in[3];
    const float* W    = (const float*)d_in[4];
    const float* bias = (const float*)d_in[5];
    float* out = (float*)d_out;

    cudaFuncSetAttribute(k_gemm, cudaFuncAttributeMaxDynamicSharedMemorySize, GEMM_DYN);
    cudaFuncSetAttribute(k_trans, cudaFuncAttributeMaxDynamicSharedMemorySize, TRANS_DYN);
    cudaFuncSetAttribute(k_final, cudaFuncAttributeMaxDynamicSharedMemorySize, FIN_DYN);

    k_convA_direct<<<(3 * 1024 * 1024 + 255) / 256, 256>>>(A0, A1, A2);
    k_transposeA_conv<<<dim3(32, 32, 3), dim3(32, 8)>>>(A0, A1, A2);
    k_convX<<<2048, 256>>>(x);
    k_convW<<<56, 256>>>(W);

    k_gemm<<<dim3(8, 4, 3), 256, GEMM_DYN>>>(0);     // (A^T)^2
    k_conv_sq<<<(3 * 1024 * 1024 + 255) / 256, 256>>>();

    k_gemm<<<dim3(48, 52, 1), 256, GEMM_DYN>>>(1);   // fused diffusion -> g_yt fp16

    k_trans<<<dim3(128, 32), 256, TRANS_DYN>>>(x);   // pack Hf
    k_final<<<dim3(104, 32), 256, FIN_DYN>>>(bias, out);
}